// round 1
// baseline (speedup 1.0000x reference)
#include <cuda_runtime.h>
#include <cuda_bf16.h>
#include <math.h>

// Problem constants
#define L_LAYERS 4
#define T_SEQ    4096
#define DM       2048
#define DH       1024
#define BN_EPS   1e-5f

// ---------------------------------------------------------------------------
// Scratch buffers (no cudaMalloc allowed) — ~256MB total, fine on GB300.
// ---------------------------------------------------------------------------
__device__ float g_x [T_SEQ * DM];   // carry
__device__ float g_xn[T_SEQ * DM];   // batchnorm output
__device__ float g_Bu[T_SEQ * DM];   // [t][0:1024]=re, [t][1024:2048]=im
__device__ float g_h [T_SEQ * DM];   // scan output, same packing
__device__ float g_y [T_SEQ * DM];   // LRU output / gelu
__device__ float g_u [T_SEQ * DM];   // GLU branch 1
__device__ float g_v [T_SEQ * DM];   // GLU branch 2
__device__ float g_Bn[DM * DM];      // packed B_norm weights (2048 x 2048)
__device__ float g_Cc[DM * DM];      // packed [C_re | -C_im] (2048 x 2048)
__device__ float g_mean[DM];
__device__ float g_var [DM];

// ---------------------------------------------------------------------------
// SGEMM (NT): C[m][n] = sum_k A[m][k] * B[n][k] (+ bias[n])
// BM=BN=64, BK=16, 256 threads, 4x4 per-thread microtile.
// M=4096, N=2048, K=2048 for every call (all dims divide tiles exactly).
// ---------------------------------------------------------------------------
__global__ __launch_bounds__(256) void sgemm_nt(
    const float* __restrict__ A, const float* __restrict__ B,
    const float* __restrict__ bias, float* __restrict__ C,
    int M, int N, int K)
{
    __shared__ float As[16][64];
    __shared__ float Bs[16][64];

    const int bm = blockIdx.y * 64;
    const int bn = blockIdx.x * 64;
    const int tid = threadIdx.x;
    const int tx = tid & 15;         // 0..15 -> n microtile
    const int ty = tid >> 4;         // 0..15 -> m microtile

    // global load mapping: 256 threads load 64 rows x 16 cols as float4
    const int lr = tid >> 2;         // 0..63 row within tile
    const int lc = (tid & 3) * 4;    // k offset 0,4,8,12

    const float* Ap = A + (size_t)(bm + lr) * K + lc;
    const float* Bp = B + (size_t)(bn + lr) * K + lc;

    float acc[4][4] = {};

    for (int k0 = 0; k0 < K; k0 += 16) {
        float4 av = *(const float4*)(Ap + k0);
        float4 bv = *(const float4*)(Bp + k0);
        As[lc + 0][lr] = av.x; As[lc + 1][lr] = av.y;
        As[lc + 2][lr] = av.z; As[lc + 3][lr] = av.w;
        Bs[lc + 0][lr] = bv.x; Bs[lc + 1][lr] = bv.y;
        Bs[lc + 2][lr] = bv.z; Bs[lc + 3][lr] = bv.w;
        __syncthreads();

        #pragma unroll
        for (int k = 0; k < 16; k++) {
            float4 a = *(const float4*)&As[k][ty * 4];
            float4 b = *(const float4*)&Bs[k][tx * 4];
            acc[0][0] += a.x * b.x; acc[0][1] += a.x * b.y;
            acc[0][2] += a.x * b.z; acc[0][3] += a.x * b.w;
            acc[1][0] += a.y * b.x; acc[1][1] += a.y * b.y;
            acc[1][2] += a.y * b.z; acc[1][3] += a.y * b.w;
            acc[2][0] += a.z * b.x; acc[2][1] += a.z * b.y;
            acc[2][2] += a.z * b.z; acc[2][3] += a.z * b.w;
            acc[3][0] += a.w * b.x; acc[3][1] += a.w * b.y;
            acc[3][2] += a.w * b.z; acc[3][3] += a.w * b.w;
        }
        __syncthreads();
    }

    float4 bb = make_float4(0.f, 0.f, 0.f, 0.f);
    if (bias) bb = *(const float4*)(bias + bn + tx * 4);

    #pragma unroll
    for (int i = 0; i < 4; i++) {
        float4 o;
        o.x = acc[i][0] + bb.x; o.y = acc[i][1] + bb.y;
        o.z = acc[i][2] + bb.z; o.w = acc[i][3] + bb.w;
        *(float4*)(C + (size_t)(bm + ty * 4 + i) * N + bn + tx * 4) = o;
    }
}

// ---------------------------------------------------------------------------
// BatchNorm over time axis (training mode, biased variance).
// ---------------------------------------------------------------------------
__global__ void bn_stats(const float* __restrict__ x)
{
    const int col = blockIdx.x * 32 + (threadIdx.x & 31);
    const int r0  = threadIdx.x >> 5;  // 0..7
    float s = 0.f, ss = 0.f;
    for (int t = r0; t < T_SEQ; t += 8) {
        float v = x[(size_t)t * DM + col];
        s += v; ss += v * v;
    }
    __shared__ float sh_s[8][32], sh_ss[8][32];
    sh_s[r0][threadIdx.x & 31]  = s;
    sh_ss[r0][threadIdx.x & 31] = ss;
    __syncthreads();
    if (r0 == 0) {
        for (int r = 1; r < 8; r++) {
            s  += sh_s[r][threadIdx.x & 31];
            ss += sh_ss[r][threadIdx.x & 31];
        }
        float mu = s / (float)T_SEQ;
        g_mean[col] = mu;
        g_var[col]  = ss / (float)T_SEQ - mu * mu;
    }
}

__global__ void bn_apply(const float* __restrict__ x, float* __restrict__ xn,
                         const float* __restrict__ w, const float* __restrict__ b)
{
    int idx = blockIdx.x * blockDim.x + threadIdx.x;
    int n = idx & (DM - 1);
    float inv = rsqrtf(g_var[n] + BN_EPS);
    xn[idx] = (x[idx] - g_mean[n]) * inv * w[n] + b[n];
}

// ---------------------------------------------------------------------------
// Weight packing kernels (per layer).
// ---------------------------------------------------------------------------
__global__ void prep_B(const float* __restrict__ B_re, const float* __restrict__ B_im,
                       const float* __restrict__ gamma_log)
{
    int idx = blockIdx.x * blockDim.x + threadIdx.x;  // over DM*DM
    int j = idx / DM;       // output row 0..2047
    int k = idx - j * DM;
    int jj = j & (DH - 1);
    float g = expf(gamma_log[jj]);
    float w = (j < DH) ? B_re[(size_t)jj * DM + k] : B_im[(size_t)jj * DM + k];
    g_Bn[idx] = w * g;
}

__global__ void prep_C(const float* __restrict__ C_re, const float* __restrict__ C_im)
{
    int idx = blockIdx.x * blockDim.x + threadIdx.x;  // over DM*DM
    int n = idx / DM;
    int k = idx - n * DM;
    float v;
    if (k < DH) v =  C_re[(size_t)n * DH + k];
    else        v = -C_im[(size_t)n * DH + (k - DH)];
    g_Cc[idx] = v;
}

// ---------------------------------------------------------------------------
// LRU scan: h_t = lam * h_{t-1} + Bu_t per complex channel (1024 channels).
// ---------------------------------------------------------------------------
__global__ void scan_kernel(const float* __restrict__ Bu, float* __restrict__ h,
                            const float* __restrict__ nu_log,
                            const float* __restrict__ theta_log)
{
    int j = blockIdx.x * blockDim.x + threadIdx.x;  // 0..1023
    float mag = expf(-expf(nu_log[j]));
    float ph  = expf(theta_log[j]);
    float lr = mag * cosf(ph);
    float li = mag * sinf(ph);
    float hr = 0.f, hi = 0.f;
    for (int t = 0; t < T_SEQ; t++) {
        float br = Bu[(size_t)t * DM + j];
        float bi = Bu[(size_t)t * DM + DH + j];
        float nhr = lr * hr - li * hi + br;
        float nhi = lr * hi + li * hr + bi;
        hr = nhr; hi = nhi;
        h[(size_t)t * DM + j]      = hr;
        h[(size_t)t * DM + DH + j] = hi;
    }
}

// ---------------------------------------------------------------------------
// Elementwise epilogues.
// ---------------------------------------------------------------------------
__global__ void post_y(float* __restrict__ y, const float* __restrict__ xn,
                       const float* __restrict__ Dv)
{
    int idx = blockIdx.x * blockDim.x + threadIdx.x;
    int n = idx & (DM - 1);
    float v = y[idx] + xn[idx] * Dv[n];
    y[idx] = 0.5f * v * (1.f + erff(v * 0.70710678118654752f));
}

__global__ void glu_combine(const float* __restrict__ x, const float* __restrict__ u,
                            const float* __restrict__ v, float* __restrict__ out)
{
    int idx = blockIdx.x * blockDim.x + threadIdx.x;
    float vv = v[idx];
    float s = 1.f / (1.f + expf(-vv));
    out[idx] = x[idx] + u[idx] * s;
}

// ---------------------------------------------------------------------------
// Launch
// ---------------------------------------------------------------------------
extern "C" void kernel_launch(void* const* d_in, const int* in_sizes, int n_in,
                              void* d_out, int out_size)
{
    const float* x_in      = (const float*)d_in[0];
    const float* enc_w     = (const float*)d_in[1];
    const float* enc_b     = (const float*)d_in[2];
    const float* nu_log    = (const float*)d_in[3];
    const float* theta_log = (const float*)d_in[4];
    const float* gamma_log = (const float*)d_in[5];
    const float* B_re      = (const float*)d_in[6];
    const float* B_im      = (const float*)d_in[7];
    const float* C_re      = (const float*)d_in[8];
    const float* C_im      = (const float*)d_in[9];
    const float* Dv        = (const float*)d_in[10];
    const float* norm_w    = (const float*)d_in[11];
    const float* norm_b    = (const float*)d_in[12];
    const float* out1_w    = (const float*)d_in[13];
    const float* out1_b    = (const float*)d_in[14];
    const float* out2_w    = (const float*)d_in[15];
    const float* out2_b    = (const float*)d_in[16];
    float* out = (float*)d_out;

    float *px, *pxn, *pBu, *ph, *py, *pu, *pv, *pBn, *pCc;
    cudaGetSymbolAddress((void**)&px,  g_x);
    cudaGetSymbolAddress((void**)&pxn, g_xn);
    cudaGetSymbolAddress((void**)&pBu, g_Bu);
    cudaGetSymbolAddress((void**)&ph,  g_h);
    cudaGetSymbolAddress((void**)&py,  g_y);
    cudaGetSymbolAddress((void**)&pu,  g_u);
    cudaGetSymbolAddress((void**)&pv,  g_v);
    cudaGetSymbolAddress((void**)&pBn, g_Bn);
    cudaGetSymbolAddress((void**)&pCc, g_Cc);

    dim3 ggrid(DM / 64, T_SEQ / 64);   // (N tiles, M tiles)
    dim3 wgrid(DM / 64, DM / 64);      // unused (all N=DM here)
    (void)wgrid; (void)n_in; (void)in_sizes; (void)out_size;
    const int EW_BLOCKS = (T_SEQ * DM) / 256;
    const int PW_BLOCKS = (DM * DM) / 256;

    // Encoder: x = x_in @ enc_w.T + enc_b
    sgemm_nt<<<ggrid, 256>>>(x_in, enc_w, enc_b, px, T_SEQ, DM, DM);

    for (int l = 0; l < L_LAYERS; l++) {
        const float* nw  = norm_w + l * DM;
        const float* nb  = norm_b + l * DM;
        const float* nu  = nu_log + l * DH;
        const float* th  = theta_log + l * DH;
        const float* gl  = gamma_log + l * DH;
        const float* bre = B_re + (size_t)l * DH * DM;
        const float* bim = B_im + (size_t)l * DH * DM;
        const float* cre = C_re + (size_t)l * DM * DH;
        const float* cim = C_im + (size_t)l * DM * DH;
        const float* dv  = Dv + l * DM;
        const float* w1  = out1_w + (size_t)l * DM * DM;
        const float* b1  = out1_b + l * DM;
        const float* w2  = out2_w + (size_t)l * DM * DM;
        const float* b2  = out2_b + l * DM;

        // BatchNorm
        bn_stats<<<DM / 32, 256>>>(px);
        bn_apply<<<EW_BLOCKS, 256>>>(px, pxn, nw, nb);

        // Pack B_norm, run Bu = xn @ Bn.T  (re|im packed in N)
        prep_B<<<PW_BLOCKS, 256>>>(bre, bim, gl);
        sgemm_nt<<<ggrid, 256>>>(pxn, pBn, nullptr, pBu, T_SEQ, DM, DM);

        // Scan
        scan_kernel<<<DH / 256, 256>>>(pBu, ph, nu, th);

        // y = Re(h @ C.T) + xn*D, then GELU
        prep_C<<<PW_BLOCKS, 256>>>(cre, cim);
        sgemm_nt<<<ggrid, 256>>>(ph, pCc, nullptr, py, T_SEQ, DM, DM);
        post_y<<<EW_BLOCKS, 256>>>(py, pxn, dv);

        // GLU
        sgemm_nt<<<ggrid, 256>>>(py, w1, b1, pu, T_SEQ, DM, DM);
        sgemm_nt<<<ggrid, 256>>>(py, w2, b2, pv, T_SEQ, DM, DM);

        float* dst = (l == L_LAYERS - 1) ? out : px;
        glu_combine<<<EW_BLOCKS, 256>>>(px, pu, pv, dst);
    }
}

// round 2
// speedup vs baseline: 2.3083x; 2.3083x over previous
#include <cuda_runtime.h>
#include <cuda_bf16.h>
#include <math.h>
#include <stdint.h>

#define L_LAYERS 4
#define T_SEQ    4096
#define DM       2048
#define DH       1024
#define KP       6144        // packed K = 3 * DM (hi*hi, hi*lo, lo*hi)
#define BN_EPS   1e-5f

// ---------------------------------------------------------------------------
// Scratch (no cudaMalloc allowed)
// ---------------------------------------------------------------------------
__device__ float g_x [T_SEQ * DM];
__device__ float g_xn[T_SEQ * DM];
__device__ float g_t1[T_SEQ * DM];     // Bu / y raw
__device__ float g_u [T_SEQ * DM];
__device__ float g_v [T_SEQ * DM];
__device__ __nv_bfloat16 g_act[(size_t)T_SEQ * KP];   // packed activations
__device__ __nv_bfloat16 g_wt [(size_t)DM * KP];      // packed weights
__device__ float g_mean[DM], g_var[DM];

// ---------------------------------------------------------------------------
// PTX helpers
// ---------------------------------------------------------------------------
__device__ __forceinline__ void cp16(uint32_t saddr, const void* g) {
    asm volatile("cp.async.cg.shared.global [%0], [%1], 16;\n" :: "r"(saddr), "l"(g));
}
__device__ __forceinline__ void cp_commit() {
    asm volatile("cp.async.commit_group;\n");
}
template<int N> __device__ __forceinline__ void cp_wait() {
    asm volatile("cp.async.wait_group %0;\n" :: "n"(N));
}
__device__ __forceinline__ void ldsm_x4(uint32_t* r, uint32_t addr) {
    asm volatile("ldmatrix.sync.aligned.m8n8.x4.shared.b16 {%0,%1,%2,%3}, [%4];\n"
                 : "=r"(r[0]), "=r"(r[1]), "=r"(r[2]), "=r"(r[3]) : "r"(addr));
}
__device__ __forceinline__ void mma_bf16(float* c, const uint32_t* a, uint32_t b0, uint32_t b1) {
    asm volatile("mma.sync.aligned.m16n8k16.row.col.f32.bf16.bf16.f32 "
                 "{%0,%1,%2,%3}, {%4,%5,%6,%7}, {%8,%9}, {%0,%1,%2,%3};\n"
                 : "+f"(c[0]), "+f"(c[1]), "+f"(c[2]), "+f"(c[3])
                 : "r"(a[0]), "r"(a[1]), "r"(a[2]), "r"(a[3]), "r"(b0), "r"(b1));
}

// ---------------------------------------------------------------------------
// bf16 split-K GEMM (NT): C[m][n] = sum_{k<KP} A[m][k]*B[n][k] (+bias[n])
// M=4096 fixed, N=2048 fixed, K=KP=6144. BM=BN=128, BK=32, 256 thr, 4 stages.
// ---------------------------------------------------------------------------
#define STAGES 4
#define BK 32
#define PADK 40
#define STAGE_BYTES (2 * 128 * PADK * 2)   // A + B halves, bf16
#define KITERS (KP / BK)                    // 192

__global__ __launch_bounds__(256) void gemm_bf16(
    const __nv_bfloat16* __restrict__ A, const __nv_bfloat16* __restrict__ B,
    const float* __restrict__ bias, float* __restrict__ C)
{
    extern __shared__ __nv_bfloat16 sh[];
    const int bm = blockIdx.y * 128, bn = blockIdx.x * 128;
    const int tid = threadIdx.x, lane = tid & 31, warp = tid >> 5;
    const int wm = (warp >> 2) * 64, wn = (warp & 3) * 32;

    uint32_t sbase = (uint32_t)__cvta_generic_to_shared(sh);

    // cp.async mapping: 256 threads, each copies 2 A rows-chunks + 2 B chunks
    const int r0 = tid >> 2, seg = (tid & 3) * 8;
    uint32_t dA0 = sbase + (r0 * PADK + seg) * 2;
    uint32_t dA1 = sbase + ((r0 + 64) * PADK + seg) * 2;
    uint32_t dB0 = sbase + (128 * PADK + r0 * PADK + seg) * 2;
    uint32_t dB1 = dB0 + 64 * PADK * 2;
    const __nv_bfloat16* gA0 = A + (size_t)(bm + r0) * KP + seg;
    const __nv_bfloat16* gA1 = A + (size_t)(bm + r0 + 64) * KP + seg;
    const __nv_bfloat16* gB0 = B + (size_t)(bn + r0) * KP + seg;
    const __nv_bfloat16* gB1 = B + (size_t)(bn + r0 + 64) * KP + seg;

    // ldmatrix per-lane offsets (bytes within a stage)
    uint32_t aoff[4], boff[2];
    #pragma unroll
    for (int mi = 0; mi < 4; mi++)
        aoff[mi] = ((wm + mi * 16 + (lane & 15)) * PADK + (lane >> 4) * 8) * 2;
    #pragma unroll
    for (int nh = 0; nh < 2; nh++)
        boff[nh] = (128 * PADK + (wn + nh * 16 + (lane >> 4) * 8 + (lane & 7)) * PADK
                    + ((lane >> 3) & 1) * 8) * 2;

    float acc[4][4][4] = {};

    auto load_stage = [&](int s) {
        uint32_t so = (uint32_t)(s & (STAGES - 1)) * STAGE_BYTES;
        int k0 = s * BK;
        cp16(dA0 + so, gA0 + k0);
        cp16(dA1 + so, gA1 + k0);
        cp16(dB0 + so, gB0 + k0);
        cp16(dB1 + so, gB1 + k0);
    };

    load_stage(0); cp_commit();
    load_stage(1); cp_commit();
    load_stage(2); cp_commit();

    for (int it = 0; it < KITERS; it++) {
        cp_wait<2>();
        __syncthreads();
        uint32_t sb = sbase + (uint32_t)(it & (STAGES - 1)) * STAGE_BYTES;

        #pragma unroll
        for (int ks = 0; ks < 2; ks++) {
            uint32_t ko = sb + ks * 32;   // 16 bf16 cols = 32 bytes
            uint32_t a[4][4], b[2][4];
            #pragma unroll
            for (int mi = 0; mi < 4; mi++) ldsm_x4(a[mi], ko + aoff[mi]);
            #pragma unroll
            for (int nh = 0; nh < 2; nh++) ldsm_x4(b[nh], ko + boff[nh]);
            #pragma unroll
            for (int mi = 0; mi < 4; mi++)
                #pragma unroll
                for (int ni = 0; ni < 4; ni++)
                    mma_bf16(acc[mi][ni], a[mi], b[ni >> 1][(ni & 1) * 2],
                             b[ni >> 1][(ni & 1) * 2 + 1]);
        }

        if (it + 3 < KITERS) load_stage(it + 3);
        cp_commit();
    }

    // epilogue
    const int er = lane >> 2, ec = (lane & 3) * 2;
    #pragma unroll
    for (int mi = 0; mi < 4; mi++) {
        int row = bm + wm + mi * 16 + er;
        #pragma unroll
        for (int ni = 0; ni < 4; ni++) {
            int col = bn + wn + ni * 8 + ec;
            float b0 = 0.f, b1 = 0.f;
            if (bias) { b0 = bias[col]; b1 = bias[col + 1]; }
            float2 v;
            v.x = acc[mi][ni][0] + b0; v.y = acc[mi][ni][1] + b1;
            *(float2*)&C[(size_t)row * DM + col] = v;
            v.x = acc[mi][ni][2] + b0; v.y = acc[mi][ni][3] + b1;
            *(float2*)&C[(size_t)(row + 8) * DM + col] = v;
        }
    }
}

// ---------------------------------------------------------------------------
// split helpers
// ---------------------------------------------------------------------------
__device__ __forceinline__ void split_act(float v, __nv_bfloat16* ap, size_t base) {
    __nv_bfloat16 h = __float2bfloat16(v);
    __nv_bfloat16 lo = __float2bfloat16(v - __bfloat162float(h));
    ap[base] = h; ap[base + DM] = h; ap[base + 2 * DM] = lo;   // [hi, hi, lo]
}
__device__ __forceinline__ void split_wt(float v, __nv_bfloat16* wp, size_t base) {
    __nv_bfloat16 h = __float2bfloat16(v);
    __nv_bfloat16 lo = __float2bfloat16(v - __bfloat162float(h));
    wp[base] = h; wp[base + DM] = lo; wp[base + 2 * DM] = h;   // [hi, lo, hi]
}

// ---------------------------------------------------------------------------
// BatchNorm
// ---------------------------------------------------------------------------
__global__ void bn_stats(const float* __restrict__ x)
{
    const int col = blockIdx.x * 32 + (threadIdx.x & 31);
    const int r0  = threadIdx.x >> 5;
    float s = 0.f, ss = 0.f;
    for (int t = r0; t < T_SEQ; t += 8) {
        float v = x[(size_t)t * DM + col];
        s += v; ss += v * v;
    }
    __shared__ float sh_s[8][32], sh_ss[8][32];
    sh_s[r0][threadIdx.x & 31]  = s;
    sh_ss[r0][threadIdx.x & 31] = ss;
    __syncthreads();
    if (r0 == 0) {
        for (int r = 1; r < 8; r++) {
            s  += sh_s[r][threadIdx.x & 31];
            ss += sh_ss[r][threadIdx.x & 31];
        }
        float mu = s / (float)T_SEQ;
        g_mean[col] = mu;
        g_var[col]  = ss / (float)T_SEQ - mu * mu;
    }
}

__global__ void bn_fuse(const float* __restrict__ x, float* __restrict__ xn,
                        __nv_bfloat16* __restrict__ ap,
                        const float* __restrict__ w, const float* __restrict__ b)
{
    int idx = blockIdx.x * blockDim.x + threadIdx.x;
    int n = idx & (DM - 1);
    int m = idx >> 11;
    float inv = rsqrtf(g_var[n] + BN_EPS);
    float v = (x[idx] - g_mean[n]) * inv * w[n] + b[n];
    xn[idx] = v;
    split_act(v, ap, (size_t)m * KP + n);
}

// ---------------------------------------------------------------------------
// Weight packing
// ---------------------------------------------------------------------------
__global__ void pack_w_plain(const float* __restrict__ W, __nv_bfloat16* __restrict__ wp)
{
    int idx = blockIdx.x * blockDim.x + threadIdx.x;   // over DM*DM
    int n = idx >> 11, k = idx & (DM - 1);
    split_wt(W[idx], wp, (size_t)n * KP + k);
}

__global__ void pack_Bn(const float* __restrict__ B_re, const float* __restrict__ B_im,
                        const float* __restrict__ gamma_log, __nv_bfloat16* __restrict__ wp)
{
    int idx = blockIdx.x * blockDim.x + threadIdx.x;
    int n = idx >> 11, k = idx & (DM - 1);
    int jj = n & (DH - 1);
    float g = expf(gamma_log[jj]);
    float v = ((n < DH) ? B_re[(size_t)jj * DM + k] : B_im[(size_t)jj * DM + k]) * g;
    split_wt(v, wp, (size_t)n * KP + k);
}

__global__ void pack_Cc(const float* __restrict__ C_re, const float* __restrict__ C_im,
                        __nv_bfloat16* __restrict__ wp)
{
    int idx = blockIdx.x * blockDim.x + threadIdx.x;
    int n = idx >> 11, k = idx & (DM - 1);
    float v = (k < DH) ? C_re[(size_t)n * DH + k] : -C_im[(size_t)n * DH + (k - DH)];
    split_wt(v, wp, (size_t)n * KP + k);
}

__global__ void pack_act_plain(const float* __restrict__ X, __nv_bfloat16* __restrict__ ap)
{
    int idx = blockIdx.x * blockDim.x + threadIdx.x;   // over T*DM
    int n = idx & (DM - 1);
    int m = idx >> 11;
    split_act(X[idx], ap, (size_t)m * KP + n);
}

// ---------------------------------------------------------------------------
// LRU scan: writes packed bf16 h directly
// ---------------------------------------------------------------------------
__global__ void scan_kernel(const float* __restrict__ Bu, __nv_bfloat16* __restrict__ hp,
                            const float* __restrict__ nu_log,
                            const float* __restrict__ theta_log)
{
    int j = blockIdx.x * blockDim.x + threadIdx.x;   // 0..1023
    float mag = expf(-expf(nu_log[j]));
    float ph  = expf(theta_log[j]);
    float lr = mag * cosf(ph);
    float li = mag * sinf(ph);
    float hr = 0.f, hi = 0.f;
    for (int t = 0; t < T_SEQ; t++) {
        float br = Bu[(size_t)t * DM + j];
        float bi = Bu[(size_t)t * DM + DH + j];
        float nhr = lr * hr - li * hi + br;
        float nhi = lr * hi + li * hr + bi;
        hr = nhr; hi = nhi;
        size_t base = (size_t)t * KP;
        split_act(hr, hp, base + j);
        split_act(hi, hp, base + DH + j);
    }
}

// ---------------------------------------------------------------------------
// Epilogues
// ---------------------------------------------------------------------------
__global__ void posty_fuse(const float* __restrict__ y, const float* __restrict__ xn,
                           const float* __restrict__ Dv, __nv_bfloat16* __restrict__ ap)
{
    int idx = blockIdx.x * blockDim.x + threadIdx.x;
    int n = idx & (DM - 1);
    int m = idx >> 11;
    float v = y[idx] + xn[idx] * Dv[n];
    float g = 0.5f * v * (1.f + erff(v * 0.70710678118654752f));
    split_act(g, ap, (size_t)m * KP + n);
}

__global__ void glu_combine(const float* __restrict__ x, const float* __restrict__ u,
                            const float* __restrict__ v, float* __restrict__ out)
{
    int idx = blockIdx.x * blockDim.x + threadIdx.x;
    float vv = v[idx];
    float s = 1.f / (1.f + expf(-vv));
    out[idx] = x[idx] + u[idx] * s;
}

// ---------------------------------------------------------------------------
// Launch
// ---------------------------------------------------------------------------
extern "C" void kernel_launch(void* const* d_in, const int* in_sizes, int n_in,
                              void* d_out, int out_size)
{
    const float* x_in      = (const float*)d_in[0];
    const float* enc_w     = (const float*)d_in[1];
    const float* enc_b     = (const float*)d_in[2];
    const float* nu_log    = (const float*)d_in[3];
    const float* theta_log = (const float*)d_in[4];
    const float* gamma_log = (const float*)d_in[5];
    const float* B_re      = (const float*)d_in[6];
    const float* B_im      = (const float*)d_in[7];
    const float* C_re      = (const float*)d_in[8];
    const float* C_im      = (const float*)d_in[9];
    const float* Dv        = (const float*)d_in[10];
    const float* norm_w    = (const float*)d_in[11];
    const float* norm_b    = (const float*)d_in[12];
    const float* out1_w    = (const float*)d_in[13];
    const float* out1_b    = (const float*)d_in[14];
    const float* out2_w    = (const float*)d_in[15];
    const float* out2_b    = (const float*)d_in[16];
    float* out = (float*)d_out;
    (void)in_sizes; (void)n_in; (void)out_size;

    float *px, *pxn, *pt1, *pu, *pv;
    __nv_bfloat16 *pact, *pwt;
    cudaGetSymbolAddress((void**)&px,   g_x);
    cudaGetSymbolAddress((void**)&pxn,  g_xn);
    cudaGetSymbolAddress((void**)&pt1,  g_t1);
    cudaGetSymbolAddress((void**)&pu,   g_u);
    cudaGetSymbolAddress((void**)&pv,   g_v);
    cudaGetSymbolAddress((void**)&pact, g_act);
    cudaGetSymbolAddress((void**)&pwt,  g_wt);

    const int SMEM = STAGES * STAGE_BYTES;   // 81920
    cudaFuncSetAttribute(gemm_bf16, cudaFuncAttributeMaxDynamicSharedMemorySize, SMEM);

    dim3 ggrid(DM / 128, T_SEQ / 128);   // (16, 32)
    const int EW = (T_SEQ * DM) / 256;
    const int PW = (DM * DM) / 256;

    // Encoder
    pack_act_plain<<<EW, 256>>>(x_in, pact);
    pack_w_plain<<<PW, 256>>>(enc_w, pwt);
    gemm_bf16<<<ggrid, 256, SMEM>>>(pact, pwt, enc_b, px);

    for (int l = 0; l < L_LAYERS; l++) {
        const float* nw  = norm_w + l * DM;
        const float* nb  = norm_b + l * DM;
        const float* nu  = nu_log + l * DH;
        const float* th  = theta_log + l * DH;
        const float* gl  = gamma_log + l * DH;
        const float* bre = B_re + (size_t)l * DH * DM;
        const float* bim = B_im + (size_t)l * DH * DM;
        const float* cre = C_re + (size_t)l * DM * DH;
        const float* cim = C_im + (size_t)l * DM * DH;
        const float* dv  = Dv + l * DM;
        const float* w1  = out1_w + (size_t)l * DM * DM;
        const float* b1  = out1_b + l * DM;
        const float* w2  = out2_w + (size_t)l * DM * DM;
        const float* b2  = out2_b + l * DM;

        bn_stats<<<DM / 32, 256>>>(px);
        bn_fuse<<<EW, 256>>>(px, pxn, pact, nw, nb);

        pack_Bn<<<PW, 256>>>(bre, bim, gl, pwt);
        gemm_bf16<<<ggrid, 256, SMEM>>>(pact, pwt, nullptr, pt1);   // Bu

        scan_kernel<<<DH / 256, 256>>>(pt1, pact, nu, th);          // h packed

        pack_Cc<<<PW, 256>>>(cre, cim, pwt);
        gemm_bf16<<<ggrid, 256, SMEM>>>(pact, pwt, nullptr, pt1);   // y raw

        posty_fuse<<<EW, 256>>>(pt1, pxn, dv, pact);                // gelu packed

        pack_w_plain<<<PW, 256>>>(w1, pwt);
        gemm_bf16<<<ggrid, 256, SMEM>>>(pact, pwt, b1, pu);
        pack_w_plain<<<PW, 256>>>(w2, pwt);
        gemm_bf16<<<ggrid, 256, SMEM>>>(pact, pwt, b2, pv);

        float* dst = (l == L_LAYERS - 1) ? out : px;
        glu_combine<<<EW, 256>>>(px, pu, pv, dst);
    }
}